// round 11
// baseline (speedup 1.0000x reference)
#include <cuda_runtime.h>
#include <cuda_fp16.h>
#include <cstdint>
#include <math.h>

constexpr int Bn = 4, Cn = 128, Hn = 256, Wn = 256;

// ---- device scratch (static; no runtime allocs) ----
static __device__ float g_att[2][(size_t)Bn * Hn * Wn];                              // 2 MB
static __device__ __align__(16) unsigned char g_xnhwc[(size_t)Bn * Hn * Wn * 256];   // 64 MB [b][h][w][128 ic] fp16
static __device__ __align__(16) unsigned char g_w[(size_t)9 * 128 * 128 * 2];        // 288 KB [tap][oc][ic] fp16
static __device__ __align__(16) __half g_f[(size_t)Bn * Cn * Hn * Wn];               // 64 MB conv+BN result, fp16

__device__ __forceinline__ unsigned short h_bits(__half h) {
    return __half_as_ushort(h);
}
__device__ __forceinline__ uint32_t smem_u32(const void* p) {
    uint32_t a;
    asm("{ .reg .u64 t; cvta.to.shared.u64 t, %1; cvt.u32.u64 %0, t; }" : "=r"(a) : "l"(p));
    return a;
}
__device__ __forceinline__ void ldsm_x4(uint32_t* r, uint32_t addr) {
    asm volatile("ldmatrix.sync.aligned.m8n8.x4.shared.b16 {%0,%1,%2,%3}, [%4];"
                 : "=r"(r[0]), "=r"(r[1]), "=r"(r[2]), "=r"(r[3]) : "r"(addr));
}
__device__ __forceinline__ void mma16816h(float* d, const uint32_t* a, const uint32_t* b) {
    asm volatile(
        "mma.sync.aligned.m16n8k16.row.col.f32.f16.f16.f32 "
        "{%0,%1,%2,%3}, {%4,%5,%6,%7}, {%8,%9}, {%0,%1,%2,%3};"
        : "+f"(d[0]), "+f"(d[1]), "+f"(d[2]), "+f"(d[3])
        : "r"(a[0]), "r"(a[1]), "r"(a[2]), "r"(a[3]), "r"(b[0]), "r"(b[1]));
}
__device__ __forceinline__ void cp16(uint32_t dst, const void* src, bool ok) {
    int sz = ok ? 16 : 0;   // src-size 0 => zero-fill (halo / padded rows)
    asm volatile("cp.async.cg.shared.global [%0], [%1], 16, %2;"
                 :: "r"(dst), "l"(src), "r"(sz) : "memory");
}
__device__ __forceinline__ void cp_commit() {
    asm volatile("cp.async.commit_group;" ::: "memory");
}
template <int N>
__device__ __forceinline__ void cp_wait() {
    asm volatile("cp.async.wait_group %0;" :: "n"(N) : "memory");
}

// ---------------------------------------------------------------------------
// Setup 1: x NCHW fp32 -> NHWC fp16  [b][h][w][128 ic]
// Read phase rotated by seg to avoid the (16*seg mod 32) bank collapse.
// ---------------------------------------------------------------------------
__global__ __launch_bounds__(256)
void xprep(const float* __restrict__ x) {
    __shared__ float tile[128][33];
    int wt = blockIdx.x, hh = blockIdx.y, b = blockIdx.z;
    int t = threadIdx.x, warp = t >> 5, lane = t & 31;
    const float* src = x + (((size_t)b * Cn + warp * 16) * Hn + hh) * Wn + wt * 32 + lane;
    #pragma unroll
    for (int k = 0; k < 16; k++) tile[warp * 16 + k][lane] = src[(size_t)k * Hn * Wn];
    __syncthreads();
    int px = t >> 3, seg = t & 7, icb = seg * 16;
    unsigned int hiv[8];
    #pragma unroll
    for (int jp = 0; jp < 8; jp++) {
        int jr = (jp + seg) & 7;            // rotated pair index (bank spread)
        __half h0 = __float2half_rn(tile[icb + 2 * jr][px]);
        __half h1 = __float2half_rn(tile[icb + 2 * jr + 1][px]);
        hiv[jr] = (unsigned)h_bits(h0) | ((unsigned)h_bits(h1) << 16);
    }
    size_t p = ((size_t)b * Hn + hh) * Wn + wt * 32 + px;
    unsigned char* dst = g_xnhwc + p * 256;
    *(uint4*)(dst + icb * 2)      = make_uint4(hiv[0], hiv[1], hiv[2], hiv[3]);
    *(uint4*)(dst + icb * 2 + 16) = make_uint4(hiv[4], hiv[5], hiv[6], hiv[7]);
}

// ---------------------------------------------------------------------------
// Setup 2: weights -> g_w[tap][oc][ic] fp16
// ---------------------------------------------------------------------------
__global__ __launch_bounds__(256)
void wprep(const float* __restrict__ wa, const float* __restrict__ wb) {
    int id = blockIdx.x * 256 + threadIdx.x;
    if (id >= 9 * 128 * 128) return;
    int tap = id / 16384, rem = id & 16383, oc = rem >> 7, ic = rem & 127;
    float w = (oc < 64) ? wa[((size_t)oc * 128 + ic) * 9 + tap]
                        : wb[((size_t)(oc - 64) * 128 + ic) * 9 + tap];
    *(unsigned short*)(g_w + (((size_t)tap * 128 + oc) * 128 + ic) * 2) =
        h_bits(__float2half_rn(w));
}

// ---------------------------------------------------------------------------
// Pass 1: fp16 mma.sync implicit-GEMM conv (256 thr, 2 CTA/SM).
// CTA = 128 oc x 128 px. 8 warps: 2(oc) x 4(px). 1 MMA per k16.
// smem: W double buffer (2 x 32KB), X single buffer (33.3KB).
// ---------------------------------------------------------------------------
constexpr int SM_W    = 0;           // buf s at SM_W + s*32768
constexpr int SM_XH   = 65536;       // 130 x 256B = 33280
constexpr int SM_LUT  = 98816;       // 3 x 128 f32 = 1536
constexpr int SM_ATT  = 100352;      // 2 x 128 f32 = 1024
constexpr int SMEM_BYTES = 101376;   // 99 KB -> 2 CTAs/SM

__device__ __forceinline__ void stage_X(uint32_t sb32, const unsigned char* xbase,
                                        int ih, int px0, int tid) {
    const bool rowok = (unsigned)ih < (unsigned)Hn;
    const unsigned char* xrow = xbase + (size_t)(ih & 255) * (Wn * 256);
    for (int idx = tid; idx < 130 * 16; idx += 256) {
        int r = idx >> 4, c = idx & 15;
        int g = px0 - 1 + r;
        bool ok = rowok && ((unsigned)g < (unsigned)Wn);
        const unsigned char* src = xrow + (size_t)(g & 255) * 256 + c * 16;
        uint32_t off = (uint32_t)(r * 256 + ((c ^ (r & 7)) << 4));
        cp16(sb32 + SM_XH + off, src, ok);
    }
}
__device__ __forceinline__ void stage_W(uint32_t sb32, int tap, int bufsel, int tid) {
    const unsigned char* wsrc = g_w + (size_t)tap * 32768;
    uint32_t wb = sb32 + SM_W + bufsel * 32768;
    for (int idx = tid; idx < 128 * 16; idx += 256) {
        int r = idx >> 4, c = idx & 15;
        uint32_t off = (uint32_t)(r * 256 + ((c ^ (r & 7)) << 4));
        cp16(wb + off, wsrc + r * 256 + c * 16, true);
    }
}

__global__ __launch_bounds__(256, 2)
void pass1_mma(
    const float* __restrict__ ba, const float* __restrict__ bb,
    const float* __restrict__ bnag, const float* __restrict__ bnabt,
    const float* __restrict__ bnam, const float* __restrict__ bnav,
    const float* __restrict__ bnbg, const float* __restrict__ bnbbt,
    const float* __restrict__ bnbm, const float* __restrict__ bnbv,
    const float* __restrict__ attaw, const float* __restrict__ attab,
    const float* __restrict__ attbw, const float* __restrict__ attbbias,
    const float* __restrict__ abnag, const float* __restrict__ abnabt,
    const float* __restrict__ abnam, const float* __restrict__ abnav,
    const float* __restrict__ abnbg, const float* __restrict__ abnbbt,
    const float* __restrict__ abnbm, const float* __restrict__ abnbv)
{
    extern __shared__ char sb[];
    const uint32_t sb32 = smem_u32(sb);

    const int tid = threadIdx.x, wid = tid >> 5, lane = tid & 31;
    const int warpM = wid & 1, warpN = wid >> 1;
    const int px0 = (blockIdx.x & 1) * 128;
    const int h = blockIdx.y, b = blockIdx.z;
    const int ocb = warpM * 64, pxb = warpN * 32;
    const unsigned char* xbase = g_xnhwc + (size_t)b * Hn * (Wn * 256);

    // per-oc BN/attention LUTs
    if (tid < 128) {
        int oc = tid; bool isB = oc >= 64; int ol = oc & 63;
        float g  = isB ? bnbg[ol]  : bnag[ol];
        float bt = isB ? bnbbt[ol] : bnabt[ol];
        float mu = isB ? bnbm[ol]  : bnam[ol];
        float vr = isB ? bnbv[ol]  : bnav[ol];
        float cb = isB ? bb[ol]    : ba[ol];
        float sc = g * rsqrtf(vr + 1e-3f);
        float* lut = (float*)(sb + SM_LUT);
        lut[oc]       = sc;
        lut[128 + oc] = (cb - mu) * sc + bt;
        lut[256 + oc] = isB ? attbw[ol] : attaw[ol];
    }

    float acc[4][4][4];
    #pragma unroll
    for (int i = 0; i < 4; i++)
        #pragma unroll
        for (int j = 0; j < 4; j++)
            #pragma unroll
            for (int k = 0; k < 4; k++) acc[i][j][k] = 0.f;

    // -------- pipeline prologue --------
    stage_X(sb32, xbase, h - 1, px0, tid);   // kh = 0
    stage_W(sb32, 0, 0, tid);
    cp_commit();                              // {X(kh0), W0}
    stage_W(sb32, 1, 1, tid);
    cp_commit();                              // {W1}

    // -------- 9-tap mainloop --------
    #pragma unroll 1
    for (int t = 0; t < 9; t++) {
        if (t == 8) cp_wait<0>(); else cp_wait<1>();
        __syncthreads();

        const int kw = t - (t / 3) * 3;
        const uint32_t wbase = sb32 + SM_W + (uint32_t)(t & 1) * 32768;

        #pragma unroll 2
        for (int kc = 0; kc < 8; kc++) {
            const int cA = kc * 2;
            uint32_t ah[4][4];
            #pragma unroll
            for (int mt = 0; mt < 4; mt++) {
                int mrow = ocb + mt * 16 + (lane & 15);
                int cc = cA + (lane >> 4);
                uint32_t off = (uint32_t)(mrow * 256 + ((cc ^ (mrow & 7)) << 4));
                ldsm_x4(ah[mt], wbase + off);
            }
            uint32_t bh[2][4];
            #pragma unroll
            for (int ntp = 0; ntp < 2; ntp++) {
                int prow = pxb + ntp * 16 + (lane & 7) + ((lane & 16) ? 8 : 0) + kw;
                int cc = cA + ((lane >> 3) & 1);
                uint32_t off = (uint32_t)(prow * 256 + ((cc ^ (prow & 7)) << 4));
                ldsm_x4(bh[ntp], sb32 + SM_XH + off);
            }
            #pragma unroll
            for (int mt = 0; mt < 4; mt++)
                #pragma unroll
                for (int nt = 0; nt < 4; nt++)
                    mma16816h(acc[mt][nt], ah[mt], &bh[nt >> 1][(nt & 1) * 2]);
        }
        __syncthreads();   // compute done before buffers are overwritten

        if (t < 8) {
            if (((t + 1) % 3) == 0) {            // next tap starts a new kh
                stage_X(sb32, xbase, h + (t + 1) / 3 - 1, px0, tid);
                cp_commit();
            }
            if (t + 2 <= 8) {
                stage_W(sb32, t + 2, t & 1, tid);
                cp_commit();
            }
        }
    }

    // ---- epilogue: BN + store f (fp16) + 1x1 attention partial ----
    const float* scl = (const float*)(sb + SM_LUT);
    const float* shl = scl + 128;
    const float* awl = scl + 256;
    float* attbuf = (float*)(sb + SM_ATT);

    #pragma unroll
    for (int nt = 0; nt < 4; nt++) {
        float s0 = 0.f, s1 = 0.f;
        const int pxl = pxb + nt * 8 + (lane & 3) * 2;
        #pragma unroll
        for (int mt = 0; mt < 4; mt++) {
            int oc0 = ocb + mt * 16 + (lane >> 2);
            int oc1 = oc0 + 8;
            float f0 = acc[mt][nt][0] * scl[oc0] + shl[oc0];
            float f1 = acc[mt][nt][1] * scl[oc0] + shl[oc0];
            float f2 = acc[mt][nt][2] * scl[oc1] + shl[oc1];
            float f3 = acc[mt][nt][3] * scl[oc1] + shl[oc1];
            s0 += awl[oc0] * f0 + awl[oc1] * f2;
            s1 += awl[oc0] * f1 + awl[oc1] * f3;
            __half* o0 = g_f + (((size_t)b * Cn + oc0) << 16) + h * 256 + px0 + pxl;
            __half* o1 = g_f + (((size_t)b * Cn + oc1) << 16) + h * 256 + px0 + pxl;
            *(__half2*)o0 = __floats2half2_rn(f0, f1);
            *(__half2*)o1 = __floats2half2_rn(f2, f3);
        }
        s0 += __shfl_xor_sync(0xffffffffu, s0, 4);
        s0 += __shfl_xor_sync(0xffffffffu, s0, 8);
        s0 += __shfl_xor_sync(0xffffffffu, s0, 16);
        s1 += __shfl_xor_sync(0xffffffffu, s1, 4);
        s1 += __shfl_xor_sync(0xffffffffu, s1, 8);
        s1 += __shfl_xor_sync(0xffffffffu, s1, 16);
        if (lane < 4) {
            attbuf[warpM * 128 + pxb + nt * 8 + lane * 2]     = s0;
            attbuf[warpM * 128 + pxb + nt * 8 + lane * 2 + 1] = s1;
        }
    }
    __syncthreads();

    if (tid < 128) {
        int px = px0 + tid;
        float pa = attbuf[tid];
        float pb = attbuf[128 + tid];
        float ghv = fabsf((float)h - 128.f + 0.5f) * (1.f / 128.f);
        float gwv = fabsf((float)px - 128.f + 0.5f) * (1.f / 128.f);
        float raA = pa + attab[0]    + attaw[64] * ghv + attaw[65] * gwv;
        float raB = pb + attbbias[0] + attbw[64] * ghv + attbw[65] * gwv;
        float aa = (raA - abnam[0]) * (abnag[0] * rsqrtf(abnav[0] + 1e-5f)) + abnabt[0];
        float ab = (raB - abnbm[0]) * (abnbg[0] * rsqrtf(abnbv[0] + 1e-5f)) + abnbbt[0];
        size_t pi = ((size_t)b * Hn + h) * Wn + px;
        g_att[0][pi] = aa;
        g_att[1][pi] = ab;
    }
}

// ---------------------------------------------------------------------------
// Pass 2: 3x3 attention conv + sigmoid; out = fp32(f_fp16) * map * scale.
// 8 px per thread (16B f loads), 16-channel chunks fully unrolled.
// grid (128, 8): blockIdx.y selects a 16-channel chunk.
// ---------------------------------------------------------------------------
__global__ __launch_bounds__(256)
void pass2_attn_scale(
    const float* __restrict__ wA, const float* __restrict__ wB,
    const float* __restrict__ s1p, const float* __restrict__ s2p,
    float* __restrict__ out)
{
    int t = blockIdx.x * 256 + threadIdx.x;          // B*H*W/8 = 32768 tasks
    int b = t >> 13, rem = t & 8191, h = rem >> 5, w8 = (rem & 31) << 3;
    const int cch = blockIdx.y;           // 0..7 -> channels [cch*16, cch*16+16)
    const bool branchA = (cch < 4);

    const float ghmax = 127.5f / 128.f, ghmin = 0.5f / 128.f;
    float prmax = sqrtf(ghmax * ghmax + ghmax * ghmax);
    float prmin = sqrtf(ghmin * ghmin + ghmin * ghmin);
    float kk = 2.f / (prmax - prmin);
    float c0 = 1.f - prmax * kk;

    const float* att = g_att[branchA ? 0 : 1] + (size_t)b * Hn * Wn;
    const float* wgt = branchA ? wA : wB;
    float scale = branchA ? s1p[0] : s2p[0];

    float s[8] = {0.f, 0.f, 0.f, 0.f, 0.f, 0.f, 0.f, 0.f};
    #pragma unroll
    for (int kh = 0; kh < 3; kh++) {
        int ih = h + kh - 1;
        if ((unsigned)ih >= (unsigned)Hn) continue;
        float ghv = fabsf((float)ih - 128.f + 0.5f) * (1.f / 128.f);
        #pragma unroll
        for (int kw = 0; kw < 3; kw++) {
            int ti = kh * 3 + kw;
            float w0 = wgt[ti], w1 = wgt[9 + ti], w2 = wgt[18 + ti], w3 = wgt[27 + ti];
            #pragma unroll
            for (int i = 0; i < 8; i++) {
                int jw = w8 + i + kw - 1;
                if ((unsigned)jw >= (unsigned)Wn) continue;
                float gwv = fabsf((float)jw - 128.f + 0.5f) * (1.f / 128.f);
                float pr = kk * sqrtf(ghv * ghv + gwv * gwv) + c0;
                float av = att[(size_t)ih * Wn + jw];
                s[i] += w0 * av + w1 * ghv + w2 * gwv + w3 * pr;
            }
        }
    }
    float m[8];
    #pragma unroll
    for (int i = 0; i < 8; i++) m[i] = scale / (1.f + __expf(-s[i]));

    const __half* fbase = g_f + (((size_t)b * Cn + cch * 16) << 16) + h * 256 + w8;
    float* base = out + (((size_t)b * Cn + cch * 16) * Hn + h) * Wn + w8;
    #pragma unroll
    for (int c = 0; c < 16; c++) {
        uint4 raw = *(const uint4*)(fbase + ((size_t)c << 16));
        float2 p0 = __half22float2(*(__half2*)&raw.x);
        float2 p1 = __half22float2(*(__half2*)&raw.y);
        float2 p2 = __half22float2(*(__half2*)&raw.z);
        float2 p3 = __half22float2(*(__half2*)&raw.w);
        float* op = base + ((size_t)c << 16);
        *(float4*)op       = make_float4(p0.x * m[0], p0.y * m[1], p1.x * m[2], p1.y * m[3]);
        *(float4*)(op + 4) = make_float4(p2.x * m[4], p2.y * m[5], p3.x * m[6], p3.y * m[7]);
    }
}

extern "C" void kernel_launch(void* const* d_in, const int* in_sizes, int n_in,
                              void* d_out, int out_size) {
    (void)in_sizes; (void)n_in; (void)out_size;
    const float* P[29];
    for (int i = 0; i < 29; i++) P[i] = (const float*)d_in[i];
    float* out = (float*)d_out;

    cudaFuncSetAttribute(pass1_mma, cudaFuncAttributeMaxDynamicSharedMemorySize, SMEM_BYTES);

    dim3 gx(8, 256, 4);
    xprep<<<gx, 256>>>(P[0]);
    wprep<<<(9 * 128 * 128 + 255) / 256, 256>>>(P[1], P[3]);
    dim3 g1(2, 256, 4);
    pass1_mma<<<g1, 256, SMEM_BYTES>>>(
        P[2], P[4],                   // conv biases a, b
        P[5], P[6], P[7], P[8],       // bn a
        P[9], P[10], P[11], P[12],    // bn b
        P[13], P[14], P[15], P[16],   // att 1x1 w/b a, b
        P[17], P[18], P[19], P[20],   // att bn a
        P[21], P[22], P[23], P[24]);  // att bn b
    dim3 g2((Bn * Hn * Wn / 8) / 256, 8);
    pass2_attn_scale<<<g2, 256>>>(P[25], P[26], P[27], P[28], out);
}

// round 13
// speedup vs baseline: 1.0499x; 1.0499x over previous
#include <cuda_runtime.h>
#include <cuda_fp16.h>
#include <cstdint>
#include <math.h>

constexpr int Bn = 4, Cn = 128, Hn = 256, Wn = 256;

// ---- device scratch (static; no runtime allocs) ----
static __device__ float g_att[2][(size_t)Bn * Hn * Wn];                              // 2 MB
static __device__ __align__(16) unsigned char g_xnhwc[(size_t)Bn * Hn * Wn * 256];   // 64 MB [b][h][w][128 ic] fp16
static __device__ __align__(16) unsigned char g_w[(size_t)9 * 128 * 128 * 2];        // 288 KB [tap][oc][ic] fp16
static __device__ __align__(16) __half g_f[(size_t)Bn * Cn * Hn * Wn];               // 64 MB conv+BN result, fp16

__device__ __forceinline__ unsigned short h_bits(__half h) {
    return __half_as_ushort(h);
}
__device__ __forceinline__ uint32_t smem_u32(const void* p) {
    uint32_t a;
    asm("{ .reg .u64 t; cvta.to.shared.u64 t, %1; cvt.u32.u64 %0, t; }" : "=r"(a) : "l"(p));
    return a;
}
__device__ __forceinline__ void ldsm_x4(uint32_t* r, uint32_t addr) {
    asm volatile("ldmatrix.sync.aligned.m8n8.x4.shared.b16 {%0,%1,%2,%3}, [%4];"
                 : "=r"(r[0]), "=r"(r[1]), "=r"(r[2]), "=r"(r[3]) : "r"(addr));
}
__device__ __forceinline__ void mma16816h(float* d, const uint32_t* a, const uint32_t* b) {
    asm volatile(
        "mma.sync.aligned.m16n8k16.row.col.f32.f16.f16.f32 "
        "{%0,%1,%2,%3}, {%4,%5,%6,%7}, {%8,%9}, {%0,%1,%2,%3};"
        : "+f"(d[0]), "+f"(d[1]), "+f"(d[2]), "+f"(d[3])
        : "r"(a[0]), "r"(a[1]), "r"(a[2]), "r"(a[3]), "r"(b[0]), "r"(b[1]));
}
__device__ __forceinline__ void cp16(uint32_t dst, const void* src, bool ok) {
    int sz = ok ? 16 : 0;   // src-size 0 => zero-fill (halo / padded rows)
    asm volatile("cp.async.cg.shared.global [%0], [%1], 16, %2;"
                 :: "r"(dst), "l"(src), "r"(sz) : "memory");
}
__device__ __forceinline__ void cp_commit() {
    asm volatile("cp.async.commit_group;" ::: "memory");
}
template <int N>
__device__ __forceinline__ void cp_wait() {
    asm volatile("cp.async.wait_group %0;" :: "n"(N) : "memory");
}

// ---------------------------------------------------------------------------
// Setup 1: x NCHW fp32 -> NHWC fp16  [b][h][w][128 ic]
// Read phase rotated by seg to avoid the (16*seg mod 32) bank collapse.
// ---------------------------------------------------------------------------
__global__ __launch_bounds__(256)
void xprep(const float* __restrict__ x) {
    __shared__ float tile[128][33];
    int wt = blockIdx.x, hh = blockIdx.y, b = blockIdx.z;
    int t = threadIdx.x, warp = t >> 5, lane = t & 31;
    const float* src = x + (((size_t)b * Cn + warp * 16) * Hn + hh) * Wn + wt * 32 + lane;
    #pragma unroll
    for (int k = 0; k < 16; k++) tile[warp * 16 + k][lane] = src[(size_t)k * Hn * Wn];
    __syncthreads();
    int px = t >> 3, seg = t & 7, icb = seg * 16;
    unsigned int hiv[8];
    #pragma unroll
    for (int jp = 0; jp < 8; jp++) {
        int jr = (jp + seg) & 7;            // rotated pair index (bank spread)
        __half h0 = __float2half_rn(tile[icb + 2 * jr][px]);
        __half h1 = __float2half_rn(tile[icb + 2 * jr + 1][px]);
        hiv[jr] = (unsigned)h_bits(h0) | ((unsigned)h_bits(h1) << 16);
    }
    size_t p = ((size_t)b * Hn + hh) * Wn + wt * 32 + px;
    unsigned char* dst = g_xnhwc + p * 256;
    *(uint4*)(dst + icb * 2)      = make_uint4(hiv[0], hiv[1], hiv[2], hiv[3]);
    *(uint4*)(dst + icb * 2 + 16) = make_uint4(hiv[4], hiv[5], hiv[6], hiv[7]);
}

// ---------------------------------------------------------------------------
// Setup 2: weights -> g_w[tap][oc][ic] fp16
// ---------------------------------------------------------------------------
__global__ __launch_bounds__(256)
void wprep(const float* __restrict__ wa, const float* __restrict__ wb) {
    int id = blockIdx.x * 256 + threadIdx.x;
    if (id >= 9 * 128 * 128) return;
    int tap = id / 16384, rem = id & 16383, oc = rem >> 7, ic = rem & 127;
    float w = (oc < 64) ? wa[((size_t)oc * 128 + ic) * 9 + tap]
                        : wb[((size_t)(oc - 64) * 128 + ic) * 9 + tap];
    *(unsigned short*)(g_w + (((size_t)tap * 128 + oc) * 128 + ic) * 2) =
        h_bits(__float2half_rn(w));
}

// ---------------------------------------------------------------------------
// Pass 1: fp16 mma.sync implicit-GEMM conv (256 thr, 2 CTA/SM).
// CTA = 128 oc x 128 px. 8 warps: 2(oc) x 4(px). 1 MMA per k16.
// smem: W double buffer (2 x 32KB), X single buffer (33.3KB).
// ---------------------------------------------------------------------------
constexpr int SM_W    = 0;           // buf s at SM_W + s*32768
constexpr int SM_XH   = 65536;       // 130 x 256B = 33280
constexpr int SM_LUT  = 98816;       // 3 x 128 f32 = 1536
constexpr int SM_ATT  = 100352;      // 2 x 128 f32 = 1024
constexpr int SMEM_BYTES = 101376;   // 99 KB -> 2 CTAs/SM

__device__ __forceinline__ void stage_X(uint32_t sb32, const unsigned char* xbase,
                                        int ih, int px0, int tid) {
    const bool rowok = (unsigned)ih < (unsigned)Hn;
    const unsigned char* xrow = xbase + (size_t)(ih & 255) * (Wn * 256);
    for (int idx = tid; idx < 130 * 16; idx += 256) {
        int r = idx >> 4, c = idx & 15;
        int g = px0 - 1 + r;
        bool ok = rowok && ((unsigned)g < (unsigned)Wn);
        const unsigned char* src = xrow + (size_t)(g & 255) * 256 + c * 16;
        uint32_t off = (uint32_t)(r * 256 + ((c ^ (r & 7)) << 4));
        cp16(sb32 + SM_XH + off, src, ok);
    }
}
__device__ __forceinline__ void stage_W(uint32_t sb32, int tap, int bufsel, int tid) {
    const unsigned char* wsrc = g_w + (size_t)tap * 32768;
    uint32_t wb = sb32 + SM_W + bufsel * 32768;
    for (int idx = tid; idx < 128 * 16; idx += 256) {
        int r = idx >> 4, c = idx & 15;
        uint32_t off = (uint32_t)(r * 256 + ((c ^ (r & 7)) << 4));
        cp16(wb + off, wsrc + r * 256 + c * 16, true);
    }
}

__global__ __launch_bounds__(256, 2)
void pass1_mma(
    const float* __restrict__ ba, const float* __restrict__ bb,
    const float* __restrict__ bnag, const float* __restrict__ bnabt,
    const float* __restrict__ bnam, const float* __restrict__ bnav,
    const float* __restrict__ bnbg, const float* __restrict__ bnbbt,
    const float* __restrict__ bnbm, const float* __restrict__ bnbv,
    const float* __restrict__ attaw, const float* __restrict__ attab,
    const float* __restrict__ attbw, const float* __restrict__ attbbias,
    const float* __restrict__ abnag, const float* __restrict__ abnabt,
    const float* __restrict__ abnam, const float* __restrict__ abnav,
    const float* __restrict__ abnbg, const float* __restrict__ abnbbt,
    const float* __restrict__ abnbm, const float* __restrict__ abnbv)
{
    extern __shared__ char sb[];
    const uint32_t sb32 = smem_u32(sb);

    const int tid = threadIdx.x, wid = tid >> 5, lane = tid & 31;
    const int warpM = wid & 1, warpN = wid >> 1;
    const int px0 = (blockIdx.x & 1) * 128;
    const int h = blockIdx.y, b = blockIdx.z;
    const int ocb = warpM * 64, pxb = warpN * 32;
    const unsigned char* xbase = g_xnhwc + (size_t)b * Hn * (Wn * 256);

    // per-oc BN/attention LUTs
    if (tid < 128) {
        int oc = tid; bool isB = oc >= 64; int ol = oc & 63;
        float g  = isB ? bnbg[ol]  : bnag[ol];
        float bt = isB ? bnbbt[ol] : bnabt[ol];
        float mu = isB ? bnbm[ol]  : bnam[ol];
        float vr = isB ? bnbv[ol]  : bnav[ol];
        float cb = isB ? bb[ol]    : ba[ol];
        float sc = g * rsqrtf(vr + 1e-3f);
        float* lut = (float*)(sb + SM_LUT);
        lut[oc]       = sc;
        lut[128 + oc] = (cb - mu) * sc + bt;
        lut[256 + oc] = isB ? attbw[ol] : attaw[ol];
    }

    float acc[4][4][4];
    #pragma unroll
    for (int i = 0; i < 4; i++)
        #pragma unroll
        for (int j = 0; j < 4; j++)
            #pragma unroll
            for (int k = 0; k < 4; k++) acc[i][j][k] = 0.f;

    // -------- pipeline prologue --------
    stage_X(sb32, xbase, h - 1, px0, tid);   // kh = 0
    stage_W(sb32, 0, 0, tid);
    cp_commit();                              // {X(kh0), W0}
    stage_W(sb32, 1, 1, tid);
    cp_commit();                              // {W1}

    // -------- 9-tap mainloop --------
    #pragma unroll 1
    for (int t = 0; t < 9; t++) {
        if (t == 8) cp_wait<0>(); else cp_wait<1>();
        __syncthreads();

        const int kw = t - (t / 3) * 3;
        const uint32_t wbase = sb32 + SM_W + (uint32_t)(t & 1) * 32768;

        #pragma unroll 2
        for (int kc = 0; kc < 8; kc++) {
            const int cA = kc * 2;
            uint32_t ah[4][4];
            #pragma unroll
            for (int mt = 0; mt < 4; mt++) {
                int mrow = ocb + mt * 16 + (lane & 15);
                int cc = cA + (lane >> 4);
                uint32_t off = (uint32_t)(mrow * 256 + ((cc ^ (mrow & 7)) << 4));
                ldsm_x4(ah[mt], wbase + off);
            }
            uint32_t bh[2][4];
            #pragma unroll
            for (int ntp = 0; ntp < 2; ntp++) {
                int prow = pxb + ntp * 16 + (lane & 7) + ((lane & 16) ? 8 : 0) + kw;
                int cc = cA + ((lane >> 3) & 1);
                uint32_t off = (uint32_t)(prow * 256 + ((cc ^ (prow & 7)) << 4));
                ldsm_x4(bh[ntp], sb32 + SM_XH + off);
            }
            #pragma unroll
            for (int mt = 0; mt < 4; mt++)
                #pragma unroll
                for (int nt = 0; nt < 4; nt++)
                    mma16816h(acc[mt][nt], ah[mt], &bh[nt >> 1][(nt & 1) * 2]);
        }
        __syncthreads();   // compute done before buffers are overwritten

        if (t < 8) {
            if (((t + 1) % 3) == 0) {            // next tap starts a new kh
                stage_X(sb32, xbase, h + (t + 1) / 3 - 1, px0, tid);
                cp_commit();
            }
            if (t + 2 <= 8) {
                stage_W(sb32, t + 2, t & 1, tid);
                cp_commit();
            }
        }
    }

    // ---- epilogue: BN + store f (fp16) + 1x1 attention partial ----
    const float* scl = (const float*)(sb + SM_LUT);
    const float* shl = scl + 128;
    const float* awl = scl + 256;
    float* attbuf = (float*)(sb + SM_ATT);

    #pragma unroll
    for (int nt = 0; nt < 4; nt++) {
        float s0 = 0.f, s1 = 0.f;
        const int pxl = pxb + nt * 8 + (lane & 3) * 2;
        #pragma unroll
        for (int mt = 0; mt < 4; mt++) {
            int oc0 = ocb + mt * 16 + (lane >> 2);
            int oc1 = oc0 + 8;
            float f0 = acc[mt][nt][0] * scl[oc0] + shl[oc0];
            float f1 = acc[mt][nt][1] * scl[oc0] + shl[oc0];
            float f2 = acc[mt][nt][2] * scl[oc1] + shl[oc1];
            float f3 = acc[mt][nt][3] * scl[oc1] + shl[oc1];
            s0 += awl[oc0] * f0 + awl[oc1] * f2;
            s1 += awl[oc0] * f1 + awl[oc1] * f3;
            __half* o0 = g_f + (((size_t)b * Cn + oc0) << 16) + h * 256 + px0 + pxl;
            __half* o1 = g_f + (((size_t)b * Cn + oc1) << 16) + h * 256 + px0 + pxl;
            *(__half2*)o0 = __floats2half2_rn(f0, f1);
            *(__half2*)o1 = __floats2half2_rn(f2, f3);
        }
        s0 += __shfl_xor_sync(0xffffffffu, s0, 4);
        s0 += __shfl_xor_sync(0xffffffffu, s0, 8);
        s0 += __shfl_xor_sync(0xffffffffu, s0, 16);
        s1 += __shfl_xor_sync(0xffffffffu, s1, 4);
        s1 += __shfl_xor_sync(0xffffffffu, s1, 8);
        s1 += __shfl_xor_sync(0xffffffffu, s1, 16);
        if (lane < 4) {
            attbuf[warpM * 128 + pxb + nt * 8 + lane * 2]     = s0;
            attbuf[warpM * 128 + pxb + nt * 8 + lane * 2 + 1] = s1;
        }
    }
    __syncthreads();

    if (tid < 128) {
        int px = px0 + tid;
        float pa = attbuf[tid];
        float pb = attbuf[128 + tid];
        float ghv = fabsf((float)h - 128.f + 0.5f) * (1.f / 128.f);
        float gwv = fabsf((float)px - 128.f + 0.5f) * (1.f / 128.f);
        float raA = pa + attab[0]    + attaw[64] * ghv + attaw[65] * gwv;
        float raB = pb + attbbias[0] + attbw[64] * ghv + attbw[65] * gwv;
        float aa = (raA - abnam[0]) * (abnag[0] * rsqrtf(abnav[0] + 1e-5f)) + abnabt[0];
        float ab = (raB - abnbm[0]) * (abnbg[0] * rsqrtf(abnbv[0] + 1e-5f)) + abnbbt[0];
        size_t pi = ((size_t)b * Hn + h) * Wn + px;
        g_att[0][pi] = aa;
        g_att[1][pi] = ab;
    }
}

// ---------------------------------------------------------------------------
// Pass 2 (R9 version): 3x3 attention conv + sigmoid; out = f_fp16 * map * scale.
// 4 px per thread; grid (256, 8): blockIdx.y selects a 16-channel chunk.
// ---------------------------------------------------------------------------
__global__ __launch_bounds__(256)
void pass2_attn_scale(
    const float* __restrict__ wA, const float* __restrict__ wB,
    const float* __restrict__ s1p, const float* __restrict__ s2p,
    float* __restrict__ out)
{
    int t = blockIdx.x * 256 + threadIdx.x;
    int b = t >> 14, rem = t & 16383, h = rem >> 6, w4 = (rem & 63) << 2;
    const int cch = blockIdx.y;           // 0..7 -> channels [cch*16, cch*16+16)
    const bool branchA = (cch < 4);

    const float ghmax = 127.5f / 128.f, ghmin = 0.5f / 128.f;
    float prmax = sqrtf(ghmax * ghmax + ghmax * ghmax);
    float prmin = sqrtf(ghmin * ghmin + ghmin * ghmin);
    float kk = 2.f / (prmax - prmin);
    float c0 = 1.f - prmax * kk;

    const float* att = g_att[branchA ? 0 : 1] + (size_t)b * Hn * Wn;
    const float* wgt = branchA ? wA : wB;
    float scale = branchA ? s1p[0] : s2p[0];

    float s[4] = {0.f, 0.f, 0.f, 0.f};
    #pragma unroll
    for (int kh = 0; kh < 3; kh++) {
        int ih = h + kh - 1;
        if ((unsigned)ih >= (unsigned)Hn) continue;
        float ghv = fabsf((float)ih - 128.f + 0.5f) * (1.f / 128.f);
        #pragma unroll
        for (int kw = 0; kw < 3; kw++) {
            int ti = kh * 3 + kw;
            float w0 = wgt[ti], w1 = wgt[9 + ti], w2 = wgt[18 + ti], w3 = wgt[27 + ti];
            #pragma unroll
            for (int i = 0; i < 4; i++) {
                int jw = w4 + i + kw - 1;
                if ((unsigned)jw >= (unsigned)Wn) continue;
                float gwv = fabsf((float)jw - 128.f + 0.5f) * (1.f / 128.f);
                float pr = kk * sqrtf(ghv * ghv + gwv * gwv) + c0;
                float av = att[(size_t)ih * Wn + jw];
                s[i] += w0 * av + w1 * ghv + w2 * gwv + w3 * pr;
            }
        }
    }
    float m[4];
    #pragma unroll
    for (int i = 0; i < 4; i++) m[i] = scale / (1.f + __expf(-s[i]));

    const __half* fbase = g_f + (((size_t)b * Cn + cch * 16) << 16) + h * 256 + w4;
    float* base = out + (((size_t)b * Cn + cch * 16) * Hn + h) * Wn + w4;
    #pragma unroll 4
    for (int c = 0; c < 16; c++) {
        uint2 raw = *(const uint2*)(fbase + ((size_t)c << 16));
        float2 p0 = __half22float2(*(__half2*)&raw.x);
        float2 p1 = __half22float2(*(__half2*)&raw.y);
        float4 v = make_float4(p0.x * m[0], p0.y * m[1], p1.x * m[2], p1.y * m[3]);
        *(float4*)(base + ((size_t)c << 16)) = v;
    }
}

extern "C" void kernel_launch(void* const* d_in, const int* in_sizes, int n_in,
                              void* d_out, int out_size) {
    (void)in_sizes; (void)n_in; (void)out_size;
    const float* P[29];
    for (int i = 0; i < 29; i++) P[i] = (const float*)d_in[i];
    float* out = (float*)d_out;

    cudaFuncSetAttribute(pass1_mma, cudaFuncAttributeMaxDynamicSharedMemorySize, SMEM_BYTES);

    dim3 gx(8, 256, 4);
    xprep<<<gx, 256>>>(P[0]);
    wprep<<<(9 * 128 * 128 + 255) / 256, 256>>>(P[1], P[3]);
    dim3 g1(2, 256, 4);
    pass1_mma<<<g1, 256, SMEM_BYTES>>>(
        P[2], P[4],                   // conv biases a, b
        P[5], P[6], P[7], P[8],       // bn a
        P[9], P[10], P[11], P[12],    // bn b
        P[13], P[14], P[15], P[16],   // att 1x1 w/b a, b
        P[17], P[18], P[19], P[20],   // att bn a
        P[21], P[22], P[23], P[24]);  // att bn b
    dim3 g2((Bn * Hn * Wn / 4) / 256, 8);
    pass2_attn_scale<<<g2, 256>>>(P[25], P[26], P[27], P[28], out);
}